// round 3
// baseline (speedup 1.0000x reference)
#include <cuda_runtime.h>
#include <cstdint>

// Problem constants
#define NPTS   32768            // 32 * 32 * 32 points
#define DIM    64               // embedding dim
#define NE     1024             // codebook size
#define HW     1024             // 32*32 spatial
#define BHW    65536            // 64 channels * 1024 hw (per-batch stride in z)
#define PTSB   32               // points per block

// Output layout (flat concat of reference return tuple, float32):
// loss[1], z_q[2097152], perplexity[1], min_encodings[33554432], indices[32768]
#define OFF_LOSS 0ULL
#define OFF_ZQ   1ULL
#define OFF_PERP 2097153ULL
#define OFF_ENC  2097154ULL
#define OFF_IDX  35651586ULL

__device__ float        d_esq[NE];
__device__ float        d_est[DIM * NE];   // transposed codebook [k][c]
__device__ unsigned int d_count[NE];
__device__ float        d_loss;

// ---------------------------------------------------------------- helpers
struct __align__(16) ull2 { unsigned long long a, b; };

static __device__ __forceinline__ unsigned long long pk2(float v) {
    unsigned long long r;
    asm("mov.b64 %0, {%1,%2};" : "=l"(r) : "f"(v), "f"(v));
    return r;
}
static __device__ __forceinline__ void ffma2(unsigned long long& d,
                                             unsigned long long a,
                                             unsigned long long b) {
    // packed 2-wide fp32 FMA (Blackwell f32x2 pipe)
    asm("fma.rn.f32x2 %0, %1, %2, %0;" : "+l"(d) : "l"(a), "l"(b));
}
static __device__ __forceinline__ float2 upk(unsigned long long v) {
    float2 f;
    asm("mov.b64 {%0,%1}, %2;" : "=f"(f.x), "=f"(f.y) : "l"(v));
    return f;
}
// monotonic float->uint mapping for ordered compare
static __device__ __forceinline__ unsigned int ordf(float x) {
    unsigned int b = __float_as_uint(x);
    return b ^ (unsigned int)(((int)b >> 31) | 0x80000000);
}

// ---------------------------------------------------------------- prep
// 16 blocks x 128 threads; block handles 64 codes. Coalesced float4 loads
// staged through padded smem; per-code sequential fp32-rn squared sum
// (identical rounding order to reference-matching R1/R2 kernels).
__global__ void prep_kernel(const float* __restrict__ emb) {
    __shared__ float sb[64][DIM + 1];        // padded: conflict-free row sums
    const int tid = threadIdx.x;
    const int c0  = blockIdx.x * 64;

    // 64 codes x 64 dims = 1024 float4; 8 per thread, coalesced
    const float4* src = (const float4*)(emb + (size_t)c0 * DIM);
    #pragma unroll
    for (int i = 0; i < 8; ++i) {
        int f  = i * 128 + tid;              // float4 index
        int c  = f >> 4;                     // 16 float4 per code row
        int k4 = f & 15;
        float4 v = src[f];
        sb[c][k4 * 4 + 0] = v.x;
        sb[c][k4 * 4 + 1] = v.y;
        sb[c][k4 * 4 + 2] = v.z;
        sb[c][k4 * 4 + 3] = v.w;
    }
    __syncthreads();

    if (tid < 64) {
        const int c = c0 + tid;
        float s = 0.f;
        #pragma unroll
        for (int k = 0; k < DIM; ++k) {
            float v = sb[tid][k];
            s = __fadd_rn(s, __fmul_rn(v, v));
            d_est[k * NE + c] = v;           // coalesced across tid per k
        }
        d_esq[c]   = s;
        d_count[c] = 0u;
        if (c == 0) d_loss = 0.f;
    }
}

// ---------------------------------------------------------------- main fused kernel
// block: 128 threads = 16 code-threads (ct) x 8 point-threads (pt_t)
// block tile: 32 points x 128 codes per chunk (8 chunks -> 1024 codes)
// thread tile: 4 points x 8 codes; f32x2 lanes = code pairs, z pre-duplicated
__global__ void __launch_bounds__(128, 4)
vq_main_kernel(const float* __restrict__ z, const float* __restrict__ emb,
               float* __restrict__ out)
{
    __shared__ __align__(16) unsigned long long zdup[DIM][PTSB]; // {v,v} 16 KB
    __shared__ __align__(16) float es[DIM][128];                 // [k][c] 32 KB
    __shared__ float zsq_s[PTSB];
    __shared__ unsigned long long red[16][PTSB];                 // 4 KB

    const int tid  = threadIdx.x;
    const int pt_t = tid & 7;     // 0..7  (point group of 4)
    const int ct   = tid >> 3;    // 0..15 (code group of 8)
    const int pt0  = blockIdx.x * PTSB;
    const int b    = pt0 >> 10;
    const int hw0  = pt0 & 1023;
    const float* zb = z + (size_t)b * BHW + hw0;

    // load z tile, pre-packed as f32x2 duplicates
    #pragma unroll
    for (int i = 0; i < 16; ++i) {
        int f = i * 128 + tid;
        int k = f >> 5, p = f & 31;
        zdup[k][p] = pk2(zb[(size_t)k * HW + p]);
    }

    // fused zero-fill of this block's one-hot rows (base is 8-mod-16 aligned)
    {
        float* encb = out + OFF_ENC + (size_t)pt0 * NE;   // 32768 floats
        if (tid == 0) {
            encb[0] = 0.f; encb[1] = 0.f;
            encb[32766] = 0.f; encb[32767] = 0.f;
        }
        float4* e4 = (float4*)(encb + 2);                 // 16B aligned
        #pragma unroll
        for (int i = 0; i < 64; ++i) {
            int j = tid + 128 * i;
            if (j < 8191) e4[j] = make_float4(0.f, 0.f, 0.f, 0.f);
        }
    }
    __syncthreads();

    // per-point ||z||^2, sequential fp32 rn (matches reference rounding)
    if (tid < PTSB) {
        float s = 0.f;
        #pragma unroll
        for (int k = 0; k < DIM; ++k) {
            float v = upk(zdup[k][tid]).x;
            s = __fadd_rn(s, __fmul_rn(v, v));
        }
        zsq_s[tid] = s;
    }

    float bestd[4];
    int   bestc[4];
    #pragma unroll
    for (int p = 0; p < 4; ++p) { bestd[p] = __int_as_float(0x7F7FFFFF); bestc[p] = 0; }

    for (int chunk = 0; chunk < 8; ++chunk) {
        __syncthreads();   // previous chunk's es consumers done (also covers zsq_s)
        // load transposed es chunk [64][128] from d_est, coalesced float4
        #pragma unroll
        for (int i = 0; i < 16; ++i) {
            int f  = i * 128 + tid;        // 0..2047 float4s
            int k  = f >> 5;               // 32 float4 per row
            int c4 = f & 31;
            *(float4*)&es[k][c4 * 4] =
                *(const float4*)&d_est[(size_t)k * NE + chunk * 128 + c4 * 4];
        }
        __syncthreads();

        unsigned long long acc[4][4];      // [point][code-pair]
        #pragma unroll
        for (int p = 0; p < 4; ++p)
            #pragma unroll
            for (int j = 0; j < 4; ++j) acc[p][j] = 0ULL;

        #pragma unroll 8
        for (int k = 0; k < DIM; ++k) {
            ull2 zA = *(const ull2*)&zdup[k][pt_t * 4];       // points 0,1
            ull2 zB = *(const ull2*)&zdup[k][pt_t * 4 + 2];   // points 2,3
            ull2 eA = *(const ull2*)&es[k][ct * 8];           // pairs 0,1
            ull2 eB = *(const ull2*)&es[k][ct * 8 + 4];       // pairs 2,3
            ffma2(acc[0][0], zA.a, eA.a); ffma2(acc[0][1], zA.a, eA.b);
            ffma2(acc[0][2], zA.a, eB.a); ffma2(acc[0][3], zA.a, eB.b);
            ffma2(acc[1][0], zA.b, eA.a); ffma2(acc[1][1], zA.b, eA.b);
            ffma2(acc[1][2], zA.b, eB.a); ffma2(acc[1][3], zA.b, eB.b);
            ffma2(acc[2][0], zB.a, eA.a); ffma2(acc[2][1], zB.a, eA.b);
            ffma2(acc[2][2], zB.a, eB.a); ffma2(acc[2][3], zB.a, eB.b);
            ffma2(acc[3][0], zB.b, eA.a); ffma2(acc[3][1], zB.b, eA.b);
            ffma2(acc[3][2], zB.b, eB.a); ffma2(acc[3][3], zB.b, eB.b);
        }

        // distances + running argmin (strict < keeps smallest code = first index)
        const int cbase = chunk * 128 + ct * 8;
        #pragma unroll
        for (int j = 0; j < 4; ++j) {
            float esq0 = __ldg(&d_esq[cbase + 2 * j]);
            float esq1 = __ldg(&d_esq[cbase + 2 * j + 1]);
            #pragma unroll
            for (int p = 0; p < 4; ++p) {
                float zq2 = zsq_s[pt_t * 4 + p];
                float2 dot = upk(acc[p][j]);
                // d = rn(rn(zsq+esq) - rn(2*dot)); 2*dot exact -> fmaf(-2,dot,t)
                float t0 = __fadd_rn(zq2, esq0);
                float d0 = fmaf(dot.x, -2.0f, t0);
                if (d0 < bestd[p]) { bestd[p] = d0; bestc[p] = cbase + 2 * j; }
                float t1 = __fadd_rn(zq2, esq1);
                float d1 = fmaf(dot.y, -2.0f, t1);
                if (d1 < bestd[p]) { bestd[p] = d1; bestc[p] = cbase + 2 * j + 1; }
            }
        }
    }

    // cross-thread argmin reduction per point (u64 key: dist then code)
    __syncthreads();
    #pragma unroll
    for (int p = 0; p < 4; ++p)
        red[ct][pt_t * 4 + p] =
            ((unsigned long long)ordf(bestd[p]) << 32) | (unsigned)bestc[p];
    __syncthreads();

    if (tid < PTSB) {
        unsigned long long bk = red[0][tid];
        #pragma unroll
        for (int t = 1; t < 16; ++t) {
            unsigned long long v = red[t][tid];
            if (v < bk) bk = v;
        }
        int idx = (int)(unsigned int)bk;
        int n   = pt0 + tid;

        out[OFF_IDX + n] = (float)idx;
        atomicAdd(&d_count[idx], 1u);
        out[OFF_ENC + (unsigned long long)n * NE + (unsigned)idx] = 1.0f;

        // z_q gather + loss partial (straight-through: z_q_out == z_q in value)
        float errsum = 0.f;
        const float* er = emb + (size_t)idx * DIM;
        float* zq = out + OFF_ZQ + (size_t)b * BHW + hw0 + tid;
        #pragma unroll
        for (int c = 0; c < DIM; ++c) {
            float e  = __ldg(er + c);
            float zv = upk(zdup[c][tid]).x;
            float df = e - zv;
            errsum   = fmaf(df, df, errsum);
            zq[(size_t)c * HW] = e;
        }
        // reduce over the 32 lanes of warp 0
        #pragma unroll
        for (int o = 16; o > 0; o >>= 1)
            errsum += __shfl_down_sync(0xFFFFFFFFu, errsum, o);
        if (tid == 0) atomicAdd(&d_loss, errsum);
    }
}

// ---------------------------------------------------------------- finalize scalars
__global__ void finalize_kernel(float* __restrict__ out) {
    __shared__ float warp_s[32];
    int t = threadIdx.x;  // 1024 threads
    float em = (float)d_count[t] * (1.0f / 32768.0f);
    float v  = em * logf(em + 1e-10f);
    #pragma unroll
    for (int o = 16; o > 0; o >>= 1) v += __shfl_down_sync(0xFFFFFFFFu, v, o);
    if ((t & 31) == 0) warp_s[t >> 5] = v;
    __syncthreads();
    if (t < 32) {
        float w = warp_s[t];
        #pragma unroll
        for (int o = 16; o > 0; o >>= 1) w += __shfl_down_sync(0xFFFFFFFFu, w, o);
        if (t == 0) {
            out[OFF_PERP] = expf(-w);
            out[OFF_LOSS] = 1.25f * d_loss * (1.0f / 2097152.0f);
        }
    }
}

// ---------------------------------------------------------------- launch
extern "C" void kernel_launch(void* const* d_in, const int* in_sizes, int n_in,
                              void* d_out, int out_size) {
    const float* z   = (const float*)d_in[0];
    const float* emb = (const float*)d_in[1];
    float*       out = (float*)d_out;

    prep_kernel<<<16, 128>>>(emb);
    vq_main_kernel<<<NPTS / PTSB, 128>>>(z, emb, out);
    finalize_kernel<<<1, 1024>>>(out);
}

// round 4
// speedup vs baseline: 1.5237x; 1.5237x over previous
#include <cuda_runtime.h>
#include <cstdint>

// Problem constants
#define NPTS   32768            // 32 * 32 * 32 points
#define DIM    64               // embedding dim
#define NE     1024             // codebook size
#define HW     1024             // 32*32 spatial
#define BHW    65536            // 64 channels * 1024 hw (per-batch stride in z)
#define PTSB   32               // points per block

// Output layout (flat concat of reference return tuple, float32):
// loss[1], z_q[2097152], perplexity[1], min_encodings[33554432], indices[32768]
#define OFF_LOSS 0ULL
#define OFF_ZQ   1ULL
#define OFF_PERP 2097153ULL
#define OFF_ENC  2097154ULL
#define OFF_IDX  35651586ULL

__device__ float        d_esq[NE];
__device__ float        d_est[DIM * NE];   // transposed codebook [k][c]
__device__ unsigned int d_count[NE];
__device__ float        d_loss;

// ---------------------------------------------------------------- helpers
static __device__ __forceinline__ unsigned long long pk2(float v) {
    unsigned long long r;
    asm("mov.b64 %0, {%1,%2};" : "=l"(r) : "f"(v), "f"(v));
    return r;
}
static __device__ __forceinline__ void ffma2(unsigned long long& d,
                                             unsigned long long a,
                                             unsigned long long b) {
    // packed 2-wide fp32 FMA (Blackwell f32x2 pipe)
    asm("fma.rn.f32x2 %0, %1, %2, %0;" : "+l"(d) : "l"(a), "l"(b));
}
static __device__ __forceinline__ float2 upk(unsigned long long v) {
    float2 f;
    asm("mov.b64 {%0,%1}, %2;" : "=f"(f.x), "=f"(f.y) : "l"(v));
    return f;
}
// monotonic float->uint mapping for ordered compare
static __device__ __forceinline__ unsigned int ordf(float x) {
    unsigned int b = __float_as_uint(x);
    return b ^ (unsigned int)(((int)b >> 31) | 0x80000000);
}

// ---------------------------------------------------------------- prep
// 16 blocks x 128 threads; block handles 64 codes. Coalesced float4 loads
// staged through padded smem; per-code sequential fp32-rn squared sum
// (identical rounding order to reference-matching kernels). Verified 5.1us.
__global__ void prep_kernel(const float* __restrict__ emb) {
    __shared__ float sb[64][DIM + 1];        // padded: conflict-free row sums
    const int tid = threadIdx.x;
    const int c0  = blockIdx.x * 64;

    // 64 codes x 64 dims = 1024 float4; 8 per thread, coalesced
    const float4* src = (const float4*)(emb + (size_t)c0 * DIM);
    #pragma unroll
    for (int i = 0; i < 8; ++i) {
        int f  = i * 128 + tid;              // float4 index
        int c  = f >> 4;                     // 16 float4 per code row
        int k4 = f & 15;
        float4 v = src[f];
        sb[c][k4 * 4 + 0] = v.x;
        sb[c][k4 * 4 + 1] = v.y;
        sb[c][k4 * 4 + 2] = v.z;
        sb[c][k4 * 4 + 3] = v.w;
    }
    __syncthreads();

    if (tid < 64) {
        const int c = c0 + tid;
        float s = 0.f;
        #pragma unroll
        for (int k = 0; k < DIM; ++k) {
            float v = sb[tid][k];
            s = __fadd_rn(s, __fmul_rn(v, v));
            d_est[k * NE + c] = v;           // coalesced across tid per k
        }
        d_esq[c]   = s;
        d_count[c] = 0u;
        if (c == 0) d_loss = 0.f;
    }
}

// ---------------------------------------------------------------- main fused kernel
// EXACT R2 structure (measured 135.9us total with slow prep).
// block: 128 threads = 16 code-threads (ct) x 8 point-threads (pt_t)
// block tile: 32 points x 128 codes per chunk (8 chunks -> 1024 codes)
// thread tile: 4 points x 8 codes; f32x2 lanes = code pairs
__global__ void __launch_bounds__(128, 4)
vq_main_kernel(const float* __restrict__ z, const float* __restrict__ emb,
               float* __restrict__ out)
{
    __shared__ __align__(16) float zs[DIM][PTSB];    // [k][pt]  8 KB, conflict-free rows
    __shared__ __align__(16) float es[DIM][128];     // [k][c]   32 KB (transposed chunk)
    __shared__ float zsq_s[PTSB];
    __shared__ unsigned long long red[16][PTSB];     // 4 KB

    const int tid  = threadIdx.x;
    const int pt_t = tid & 7;     // 0..7  (point group of 4)
    const int ct   = tid >> 3;    // 0..15 (code group of 8)
    const int pt0  = blockIdx.x * PTSB;
    const int b    = pt0 >> 10;
    const int hw0  = pt0 & 1023;
    const float* zb = z + (size_t)b * BHW + hw0;

    // load z tile [k][pt] (coalesced: one row per warp-iteration)
    #pragma unroll
    for (int i = 0; i < 16; ++i) {
        int f = i * 128 + tid;
        int k = f >> 5, p = f & 31;
        zs[k][p] = zb[(size_t)k * HW + p];
    }

    // fused zero-fill of this block's one-hot rows (base is 8-mod-16 aligned)
    {
        float* encb = out + OFF_ENC + (size_t)pt0 * NE;   // 32768 floats
        if (tid == 0) {
            encb[0] = 0.f; encb[1] = 0.f;
            encb[32766] = 0.f; encb[32767] = 0.f;
        }
        float4* e4 = (float4*)(encb + 2);                 // 16B aligned
        #pragma unroll
        for (int i = 0; i < 64; ++i) {
            int j = tid + 128 * i;
            if (j < 8191) e4[j] = make_float4(0.f, 0.f, 0.f, 0.f);
        }
    }
    __syncthreads();

    // per-point ||z||^2, sequential fp32 rn (matches reference rounding)
    if (tid < PTSB) {
        float s = 0.f;
        #pragma unroll
        for (int k = 0; k < DIM; ++k) {
            float v = zs[k][tid];
            s = __fadd_rn(s, __fmul_rn(v, v));
        }
        zsq_s[tid] = s;
    }

    unsigned long long best[4];
    #pragma unroll
    for (int p = 0; p < 4; ++p) best[p] = 0xFFFFFFFFFFFFFFFFULL;

    for (int chunk = 0; chunk < 8; ++chunk) {
        __syncthreads();   // previous chunk's es consumers done (also covers zsq_s)
        // load transposed es chunk [64][128] from d_est, coalesced float4
        #pragma unroll
        for (int i = 0; i < 16; ++i) {
            int f  = i * 128 + tid;        // 0..2047 float4s
            int k  = f >> 5;               // 32 float4 per row
            int c4 = f & 31;
            *(float4*)&es[k][c4 * 4] =
                *(const float4*)&d_est[(size_t)k * NE + chunk * 128 + c4 * 4];
        }
        __syncthreads();

        unsigned long long acc[4][4];      // [point][code-pair]
        #pragma unroll
        for (int p = 0; p < 4; ++p)
            #pragma unroll
            for (int j = 0; j < 4; ++j) acc[p][j] = 0ULL;

        #pragma unroll 8
        for (int k = 0; k < DIM; ++k) {
            float4 zv = *(const float4*)&zs[k][pt_t * 4];
            unsigned long long z0 = pk2(zv.x), z1 = pk2(zv.y);
            unsigned long long z2 = pk2(zv.z), z3 = pk2(zv.w);
            const unsigned long long* ep =
                (const unsigned long long*)&es[k][ct * 8];
            #pragma unroll
            for (int j = 0; j < 4; ++j) {
                unsigned long long e2 = ep[j];     // codes (2j, 2j+1) of group
                ffma2(acc[0][j], z0, e2);
                ffma2(acc[1][j], z1, e2);
                ffma2(acc[2][j], z2, e2);
                ffma2(acc[3][j], z3, e2);
            }
        }

        // distances + running argmin (u64 key -> first-index tie-break)
        const int cbase = chunk * 128 + ct * 8;
        #pragma unroll
        for (int j = 0; j < 4; ++j) {
            float esq0 = __ldg(&d_esq[cbase + 2 * j]);
            float esq1 = __ldg(&d_esq[cbase + 2 * j + 1]);
            #pragma unroll
            for (int p = 0; p < 4; ++p) {
                float zq2 = zsq_s[pt_t * 4 + p];
                float2 dot = upk(acc[p][j]);
                {
                    float d = __fadd_rn(__fadd_rn(zq2, esq0), -2.0f * dot.x);
                    unsigned long long k64 =
                        ((unsigned long long)ordf(d) << 32) | (unsigned)(cbase + 2 * j);
                    if (k64 < best[p]) best[p] = k64;
                }
                {
                    float d = __fadd_rn(__fadd_rn(zq2, esq1), -2.0f * dot.y);
                    unsigned long long k64 =
                        ((unsigned long long)ordf(d) << 32) | (unsigned)(cbase + 2 * j + 1);
                    if (k64 < best[p]) best[p] = k64;
                }
            }
        }
    }

    // cross-thread argmin reduction per point
    __syncthreads();
    #pragma unroll
    for (int p = 0; p < 4; ++p) red[ct][pt_t * 4 + p] = best[p];
    __syncthreads();

    if (tid < PTSB) {
        unsigned long long bk = red[0][tid];
        #pragma unroll
        for (int t = 1; t < 16; ++t) {
            unsigned long long v = red[t][tid];
            if (v < bk) bk = v;
        }
        int idx = (int)(unsigned int)bk;
        int n   = pt0 + tid;

        out[OFF_IDX + n] = (float)idx;
        atomicAdd(&d_count[idx], 1u);
        out[OFF_ENC + (unsigned long long)n * NE + (unsigned)idx] = 1.0f;

        // z_q gather + loss partial (straight-through: z_q_out == z_q in value)
        float errsum = 0.f;
        const float* er = emb + (size_t)idx * DIM;
        float* zq = out + OFF_ZQ + (size_t)b * BHW + hw0 + tid;
        #pragma unroll
        for (int c = 0; c < DIM; ++c) {
            float e  = __ldg(er + c);
            float zv = zs[c][tid];
            float df = e - zv;
            errsum   = fmaf(df, df, errsum);
            zq[(size_t)c * HW] = e;
        }
        // reduce over the 32 lanes of warp 0
        #pragma unroll
        for (int o = 16; o > 0; o >>= 1)
            errsum += __shfl_down_sync(0xFFFFFFFFu, errsum, o);
        if (tid == 0) atomicAdd(&d_loss, errsum);
    }
}

// ---------------------------------------------------------------- finalize scalars
__global__ void finalize_kernel(float* __restrict__ out) {
    __shared__ float warp_s[32];
    int t = threadIdx.x;  // 1024 threads
    float em = (float)d_count[t] * (1.0f / 32768.0f);
    float v  = em * logf(em + 1e-10f);
    #pragma unroll
    for (int o = 16; o > 0; o >>= 1) v += __shfl_down_sync(0xFFFFFFFFu, v, o);
    if ((t & 31) == 0) warp_s[t >> 5] = v;
    __syncthreads();
    if (t < 32) {
        float w = warp_s[t];
        #pragma unroll
        for (int o = 16; o > 0; o >>= 1) w += __shfl_down_sync(0xFFFFFFFFu, w, o);
        if (t == 0) {
            out[OFF_PERP] = expf(-w);
            out[OFF_LOSS] = 1.25f * d_loss * (1.0f / 2097152.0f);
        }
    }
}

// ---------------------------------------------------------------- launch
extern "C" void kernel_launch(void* const* d_in, const int* in_sizes, int n_in,
                              void* d_out, int out_size) {
    const float* z   = (const float*)d_in[0];
    const float* emb = (const float*)d_in[1];
    float*       out = (float*)d_out;

    prep_kernel<<<16, 128>>>(emb);
    vq_main_kernel<<<NPTS / PTSB, 128>>>(z, emb, out);
    finalize_kernel<<<1, 1024>>>(out);
}